// round 12
// baseline (speedup 1.0000x reference)
#include <cuda_runtime.h>
#include <cuda_bf16.h>
#include <cstdint>
#include <cstddef>

// ---------------------------------------------------------------------------
// LuongAttention via bf16 hi/lo 3-pass mma.sync (HMMA).
// R11: 128x128 CTA with 2x2 warps of 64x64 tiles (128 thr), 3-stage mbarrier
//      ring (produced count 128, consumed count 4 via lane0-elect arrive),
//      2 CTAs/SM. MMA:ldsm ratio 6:1.
// ---------------------------------------------------------------------------

#define B_DIM 16
#define TQ 2048
#define TV 2048
#define D_DIM 1024
#define UNITS 1024

typedef __nv_bfloat16 bf16;

#define NQ ((size_t)B_DIM * TQ * UNITS)
#define NV ((size_t)B_DIM * TV * D_DIM)
#define NK ((size_t)B_DIM * TV * UNITS)
#define NS ((size_t)B_DIM * TQ * TV)

__device__ bf16 g_Qhi[NQ], g_Qlo[NQ];
__device__ bf16 g_Vhi[NV], g_Vlo[NV];
__device__ bf16 g_VThi[NV], g_VTlo[NV];     // values^T per batch: [D, TV]
__device__ bf16 g_Khi[NK], g_Klo[NK];
__device__ bf16 g_WThi[D_DIM * UNITS], g_WTlo[D_DIM * UNITS];   // W^T: [U, D]
__device__ bf16 g_Ahi[NS], g_Alo[NS];

// ---------------------------------------------------------------------------
__device__ __forceinline__ uint32_t smem_u32(const void* p) {
    uint32_t a;
    asm("{ .reg .u64 t; cvta.to.shared.u64 t, %1; cvt.u32.u64 %0, t; }"
        : "=r"(a) : "l"(p));
    return a;
}

#define CP_ASYNC16(dst, src) \
    asm volatile("cp.async.cg.shared.global [%0], [%1], 16;" \
                 :: "r"(dst), "l"(src) : "memory")

#define MBAR_INIT(a, c) \
    asm volatile("mbarrier.init.shared.b64 [%0], %1;" :: "r"(a), "r"(c) : "memory")
#define MBAR_ARRIVE(a) \
    asm volatile("mbarrier.arrive.shared.b64 _, [%0];" :: "r"(a) : "memory")
#define CP_MBAR_ARRIVE(a) \
    asm volatile("cp.async.mbarrier.arrive.noinc.shared.b64 [%0];" :: "r"(a) : "memory")

#define MBAR_WAIT(a, par) do {                                            \
    uint32_t _m = (a), _p = (uint32_t)(par), _d;                          \
    asm volatile("{\n\t.reg .pred p;\n\t"                                 \
        "mbarrier.try_wait.parity.acquire.cta.shared::cta.b64 p, [%1], %2;\n\t" \
        "selp.b32 %0, 1, 0, p;\n\t}" : "=r"(_d) : "r"(_m), "r"(_p) : "memory"); \
    if (!_d) {                                                            \
        asm volatile("{\n\t.reg .pred P1;\n\t"                            \
            "WL_%=:\n\t"                                                  \
            "mbarrier.try_wait.parity.acquire.cta.shared::cta.b64 P1, [%0], %1, 0x989680;\n\t" \
            "@P1 bra.uni WD_%=;\n\tbra.uni WL_%=;\n\tWD_%=:\n\t}"         \
            :: "r"(_m), "r"(_p) : "memory");                              \
    } } while (0)

__device__ __forceinline__ void ldsm4(uint32_t& r0, uint32_t& r1,
                                      uint32_t& r2, uint32_t& r3, uint32_t addr) {
    asm volatile("ldmatrix.sync.aligned.m8n8.x4.shared.b16 {%0,%1,%2,%3}, [%4];"
                 : "=r"(r0), "=r"(r1), "=r"(r2), "=r"(r3) : "r"(addr));
}

__device__ __forceinline__ void mma16816(float* d, const uint32_t* a, const uint32_t* b) {
    asm volatile("mma.sync.aligned.m16n8k16.row.col.f32.bf16.bf16.f32 "
                 "{%0,%1,%2,%3},{%4,%5,%6,%7},{%8,%9},{%0,%1,%2,%3};"
                 : "+f"(d[0]), "+f"(d[1]), "+f"(d[2]), "+f"(d[3])
                 : "r"(a[0]), "r"(a[1]), "r"(a[2]), "r"(a[3]), "r"(b[0]), "r"(b[1]));
}

// ---------------------------------------------------------------------------
// SMEM: rows of 64 B (32 bf16), XOR swizzle: 16B-chunk c of row r at position
// c ^ ((r>>1)&3). Stage: Ahi|Alo|Bhi|Blo, each 8192 B. Stage = 32 KB, x3 ring.
// Barriers: produced[3], consumed[3].
// ---------------------------------------------------------------------------
#define OFF_AHI 0u
#define OFF_ALO 8192u
#define OFF_BHI 16384u
#define OFF_BLO 24576u
#define ST_SZ   32768u
#define SM_PROD (3u * ST_SZ)
#define SM_CONS (3u * ST_SZ + 24u)
#define SM_TOTAL (3u * ST_SZ + 64u)

// C[M,N] = (Ahi+Alo)[M,K] @ (Bhi+Blo)[N,K]^T  (3-pass), batched via blockIdx.z.
// CTA tile 128x128, 4 warps, warp tile 64x64 (2x2). EPI=0: fp32 C. EPI=1:
// +bias, split to Chi/Clo bf16.
template <int EPI>
__global__ void __launch_bounds__(128, 2)
hmma_gemm_kernel(const bf16* __restrict__ Ahi_, const bf16* __restrict__ Alo_,
                 const bf16* __restrict__ Bhi_, const bf16* __restrict__ Blo_,
                 const float* __restrict__ bias,
                 float* __restrict__ Cf_, bf16* __restrict__ Chi_, bf16* __restrict__ Clo_,
                 int M, int N, int K,
                 size_t sA, size_t sB, size_t sC) {
    extern __shared__ char smc[];
    const uint32_t sb = smem_u32(smc);
    const int tid = threadIdx.x, lane = tid & 31, wid = tid >> 5;
    const int wm = wid >> 1, wn = wid & 1;        // 2x2 warps, tile 64x64
    const int bn = blockIdx.x, bm = blockIdx.y, bz = blockIdx.z;

    const bf16* Ah = Ahi_ + (size_t)bz * sA;
    const bf16* Al = Alo_ + (size_t)bz * sA;
    const bf16* Bh = Bhi_ + (size_t)bz * sB;
    const bf16* Bl = Blo_ + (size_t)bz * sB;

    float acc[4][8][4];
#pragma unroll
    for (int i = 0; i < 4; ++i)
#pragma unroll
        for (int j = 0; j < 8; ++j)
#pragma unroll
            for (int p = 0; p < 4; ++p) acc[i][j][p] = 0.0f;

    // ---- writer coords: each thread owns one 64-B row per operand ----
    const int lr = tid;                        // row 0..127
    const int wsw = (lr >> 1) & 3;             // swizzle key
    const uint32_t wr = (uint32_t)lr * 64;
    const uint32_t sw0 = wr + (uint32_t)(((0 ^ wsw)) * 16);
    const uint32_t sw1 = wr + (uint32_t)(((1 ^ wsw)) * 16);
    const uint32_t sw2 = wr + (uint32_t)(((2 ^ wsw)) * 16);
    const uint32_t sw3 = wr + (uint32_t)(((3 ^ wsw)) * 16);

    // ---- reader coords ----
    const int row0a = wm * 64 + (lane & 15);
    const int c0a = lane >> 4;
    const int sa = (row0a >> 1) & 3;
    const uint32_t axk[2] = { (uint32_t)(((c0a + 0) ^ sa) * 16),
                              (uint32_t)(((c0a + 2) ^ sa) * 16) };
    const uint32_t abase = (uint32_t)row0a * 64;
    const int row0b = wn * 64 + ((lane >> 4) << 3) + (lane & 7);
    const int c0b = (lane >> 3) & 1;
    const int sbw = (row0b >> 1) & 3;
    const uint32_t bxk[2] = { (uint32_t)(((c0b + 0) ^ sbw) * 16),
                              (uint32_t)(((c0b + 2) ^ sbw) * 16) };
    const uint32_t bbase = (uint32_t)row0b * 64;

    const int nk = K / 32;

    auto load_stage = [&](int kt, uint32_t st) {
        const size_t kc = (size_t)kt * 32;
        const size_t gA = (size_t)(bm * 128 + lr) * K + kc;
        const size_t gB = (size_t)(bn * 128 + lr) * K + kc;
        CP_ASYNC16(st + OFF_AHI + sw0, Ah + gA);
        CP_ASYNC16(st + OFF_AHI + sw1, Ah + gA + 8);
        CP_ASYNC16(st + OFF_AHI + sw2, Ah + gA + 16);
        CP_ASYNC16(st + OFF_AHI + sw3, Ah + gA + 24);
        CP_ASYNC16(st + OFF_ALO + sw0, Al + gA);
        CP_ASYNC16(st + OFF_ALO + sw1, Al + gA + 8);
        CP_ASYNC16(st + OFF_ALO + sw2, Al + gA + 16);
        CP_ASYNC16(st + OFF_ALO + sw3, Al + gA + 24);
        CP_ASYNC16(st + OFF_BHI + sw0, Bh + gB);
        CP_ASYNC16(st + OFF_BHI + sw1, Bh + gB + 8);
        CP_ASYNC16(st + OFF_BHI + sw2, Bh + gB + 16);
        CP_ASYNC16(st + OFF_BHI + sw3, Bh + gB + 24);
        CP_ASYNC16(st + OFF_BLO + sw0, Bl + gB);
        CP_ASYNC16(st + OFF_BLO + sw1, Bl + gB + 8);
        CP_ASYNC16(st + OFF_BLO + sw2, Bl + gB + 16);
        CP_ASYNC16(st + OFF_BLO + sw3, Bl + gB + 24);
    };

    // ---- barrier init, prologue fills for stages 0 and 1 ----
    if (tid == 0) {
#pragma unroll
        for (int s = 0; s < 3; ++s) {
            MBAR_INIT(sb + SM_PROD + s * 8, 128);   // all threads' cp.async arrive
            MBAR_INIT(sb + SM_CONS + s * 8, 4);     // lane0 of each warp arrives
        }
    }
    __syncthreads();

    load_stage(0, sb);
    CP_MBAR_ARRIVE(sb + SM_PROD + 0);
    load_stage(1, sb + ST_SZ);
    CP_MBAR_ARRIVE(sb + SM_PROD + 8);

    int rs = 0, rp = 0;        // read stage/parity
    int ws = 2, wp = 1;        // write stage/parity

    for (int kt = 0; kt < nk; ++kt) {
        const uint32_t s0 = sb + (uint32_t)rs * ST_SZ;
        MBAR_WAIT(sb + SM_PROD + rs * 8, rp);

#pragma unroll
        for (int ks = 0; ks < 2; ++ks) {
            uint32_t ahf[4][4], bhf[4][4], blf[4][4], alf[4][4];

            // critical-path burst: all bhf (needed by mi=0) + ahf[0]
#pragma unroll
            for (int np = 0; np < 4; ++np)
                ldsm4(bhf[np][0], bhf[np][1], bhf[np][2], bhf[np][3],
                      s0 + OFF_BHI + bbase + (uint32_t)(np * 16 * 64) + bxk[ks]);
            ldsm4(ahf[0][0], ahf[0][1], ahf[0][2], ahf[0][3],
                  s0 + OFF_AHI + abase + axk[ks]);

            // pass 1 (hi*hi): 8 MMAs per mi; pace remaining ldsm
#pragma unroll
            for (int mi = 0; mi < 4; ++mi) {
                if (mi < 3) {
                    ldsm4(ahf[mi + 1][0], ahf[mi + 1][1], ahf[mi + 1][2], ahf[mi + 1][3],
                          s0 + OFF_AHI + abase + (uint32_t)((mi + 1) * 16 * 64) + axk[ks]);
                }
                if (mi >= 2) {
#pragma unroll
                    for (int np = 0; np < 2; ++np) {
                        const int b = (mi - 2) * 2 + np;
                        ldsm4(blf[b][0], blf[b][1], blf[b][2], blf[b][3],
                              s0 + OFF_BLO + bbase + (uint32_t)(b * 16 * 64) + bxk[ks]);
                    }
                }
#pragma unroll
                for (int ni = 0; ni < 8; ++ni)
                    mma16816(acc[mi][ni], ahf[mi], &bhf[ni >> 1][(ni & 1) * 2]);
            }

            // pass 2 (hi*lo): pace alf ldsm (used only in pass 3)
#pragma unroll
            for (int mi = 0; mi < 4; ++mi) {
                ldsm4(alf[mi][0], alf[mi][1], alf[mi][2], alf[mi][3],
                      s0 + OFF_ALO + abase + (uint32_t)(mi * 16 * 64) + axk[ks]);
#pragma unroll
                for (int ni = 0; ni < 8; ++ni)
                    mma16816(acc[mi][ni], ahf[mi], &blf[ni >> 1][(ni & 1) * 2]);
            }

            // producer block once per kt, between pass2 and pass3 of ks==0
            if (ks == 0 && kt + 2 < nk) {
                MBAR_WAIT(sb + SM_CONS + ws * 8, wp);
                load_stage(kt + 2, sb + (uint32_t)ws * ST_SZ);
                CP_MBAR_ARRIVE(sb + SM_PROD + ws * 8);
            }

            // pass 3 (lo*hi): all frags resident, dense MMA
#pragma unroll
            for (int mi = 0; mi < 4; ++mi)
#pragma unroll
                for (int ni = 0; ni < 8; ++ni)
                    mma16816(acc[mi][ni], alf[mi], &bhf[ni >> 1][(ni & 1) * 2]);
        }

        // reads of stage rs complete; mma.sync is warp-synchronous, so lane0
        // arriving proves the whole warp's ldsm of this stage are drained.
        if (lane == 0) MBAR_ARRIVE(sb + SM_CONS + rs * 8);

        if (++rs == 3) { rs = 0; rp ^= 1; }
        if (++ws == 3) { ws = 0; wp ^= 1; }
    }

    // ---- epilogue ----
    const int row0 = bm * 128 + wm * 64 + (lane >> 2);
    const int col0 = bn * 128 + wn * 64 + (lane & 3) * 2;
#pragma unroll
    for (int mi = 0; mi < 4; ++mi)
#pragma unroll
        for (int h = 0; h < 2; ++h) {
            const int row = row0 + mi * 16 + h * 8;
#pragma unroll
            for (int ni = 0; ni < 8; ++ni) {
                const int col = col0 + ni * 8;
                const float v0 = acc[mi][ni][2 * h];
                const float v1 = acc[mi][ni][2 * h + 1];
                if (EPI == 0) {
                    float2 o; o.x = v0; o.y = v1;
                    *(float2*)(Cf_ + (size_t)bz * sC + (size_t)row * N + col) = o;
                } else {
                    const float f0 = v0 + bias[col];
                    const float f1 = v1 + bias[col + 1];
                    const bf16 h0 = __float2bfloat16_rn(f0);
                    const bf16 h1 = __float2bfloat16_rn(f1);
                    __nv_bfloat162 hh, ll;
                    hh.x = h0; hh.y = h1;
                    ll.x = __float2bfloat16_rn(f0 - __bfloat162float(h0));
                    ll.y = __float2bfloat16_rn(f1 - __bfloat162float(h1));
                    const size_t o = (size_t)row * N + col;
                    *(__nv_bfloat162*)(Chi_ + o) = hh;
                    *(__nv_bfloat162*)(Clo_ + o) = ll;
                }
            }
        }
}

// ---------------------------------------------------------------------------
__global__ void split_kernel(const float* __restrict__ x,
                             bf16* __restrict__ hi, bf16* __restrict__ lo, size_t n4) {
    const size_t i = (size_t)blockIdx.x * blockDim.x + threadIdx.x;
    if (i >= n4) return;
    const float4 v = ((const float4*)x)[i];
    const float f[4] = {v.x, v.y, v.z, v.w};
    __nv_bfloat162 h2[2], l2[2];
#pragma unroll
    for (int j = 0; j < 2; ++j) {
        const bf16 h0 = __float2bfloat16_rn(f[2 * j]);
        const bf16 h1 = __float2bfloat16_rn(f[2 * j + 1]);
        h2[j].x = h0; h2[j].y = h1;
        l2[j].x = __float2bfloat16_rn(f[2 * j] - __bfloat162float(h0));
        l2[j].y = __float2bfloat16_rn(f[2 * j + 1] - __bfloat162float(h1));
    }
    ((__nv_bfloat162*)hi)[2 * i] = h2[0];
    ((__nv_bfloat162*)hi)[2 * i + 1] = h2[1];
    ((__nv_bfloat162*)lo)[2 * i] = l2[0];
    ((__nv_bfloat162*)lo)[2 * i + 1] = l2[1];
}

__global__ void transpose_split_kernel(const float* __restrict__ in,
                                       bf16* __restrict__ shi, bf16* __restrict__ slo,
                                       bf16* __restrict__ thi, bf16* __restrict__ tlo,
                                       int rows, int cols) {
    __shared__ float tile[32][33];
    const int tx = threadIdx.x, ty = threadIdx.y;
    const int bx = blockIdx.x, by = blockIdx.y, bz = blockIdx.z;
    const size_t base = (size_t)bz * rows * cols;
    const int x = bx * 32 + tx;

#pragma unroll
    for (int j = 0; j < 4; ++j) {
        const int r = by * 32 + ty + j * 8;
        const float v = in[base + (size_t)r * cols + x];
        tile[ty + j * 8][tx] = v;
        if (shi) {
            const bf16 h = __float2bfloat16_rn(v);
            shi[base + (size_t)r * cols + x] = h;
            slo[base + (size_t)r * cols + x] =
                __float2bfloat16_rn(v - __bfloat162float(h));
        }
    }
    __syncthreads();
#pragma unroll
    for (int j = 0; j < 4; ++j) {
        const int r = ty + j * 8;
        const float v = tile[tx][r];
        const int orow = bx * 32 + r;
        const int ocol = by * 32 + tx;
        const bf16 h = __float2bfloat16_rn(v);
        thi[base + (size_t)orow * rows + ocol] = h;
        tlo[base + (size_t)orow * rows + ocol] =
            __float2bfloat16_rn(v - __bfloat162float(h));
    }
}

__global__ void softmax_split_kernel(float* __restrict__ S,
                                     bf16* __restrict__ Ahi, bf16* __restrict__ Alo) {
    const int tid = threadIdx.x;
    const size_t rowoff = (size_t)blockIdx.x * TV;
    float* p = S + rowoff;

    float v[8];
    {
        const float4 x0 = *(const float4*)(p + tid * 8);
        const float4 x1 = *(const float4*)(p + tid * 8 + 4);
        v[0] = x0.x; v[1] = x0.y; v[2] = x0.z; v[3] = x0.w;
        v[4] = x1.x; v[5] = x1.y; v[6] = x1.z; v[7] = x1.w;
    }

    __shared__ float red[16];
    const int lane = tid & 31, wid = tid >> 5;

    float m = v[0];
#pragma unroll
    for (int i = 1; i < 8; ++i) m = fmaxf(m, v[i]);
#pragma unroll
    for (int o = 16; o > 0; o >>= 1) m = fmaxf(m, __shfl_xor_sync(0xffffffffu, m, o));
    if (lane == 0) red[wid] = m;
    __syncthreads();
    if (tid == 0) {
        float mm = red[0];
#pragma unroll
        for (int i = 1; i < 8; ++i) mm = fmaxf(mm, red[i]);
        red[0] = mm;
    }
    __syncthreads();
    m = red[0];

    float s = 0.0f;
#pragma unroll
    for (int i = 0; i < 8; ++i) { v[i] = __expf(v[i] - m); s += v[i]; }
#pragma unroll
    for (int o = 16; o > 0; o >>= 1) s += __shfl_xor_sync(0xffffffffu, s, o);
    if (lane == 0) red[8 + wid] = s;
    __syncthreads();
    if (tid == 0) {
        float ss = red[8];
#pragma unroll
        for (int i = 1; i < 8; ++i) ss += red[8 + i];
        red[8] = ss;
    }
    __syncthreads();
    const float inv = 1.0f / red[8];

    float y[8];
#pragma unroll
    for (int i = 0; i < 8; ++i) y[i] = v[i] * inv;

    float4 o0, o1;
    o0.x = y[0]; o0.y = y[1]; o0.z = y[2]; o0.w = y[3];
    o1.x = y[4]; o1.y = y[5]; o1.z = y[6]; o1.w = y[7];
    *(float4*)(p + tid * 8) = o0;
    *(float4*)(p + tid * 8 + 4) = o1;

#pragma unroll
    for (int j = 0; j < 4; ++j) {
        const bf16 h0 = __float2bfloat16_rn(y[2 * j]);
        const bf16 h1 = __float2bfloat16_rn(y[2 * j + 1]);
        __nv_bfloat162 h2; h2.x = h0; h2.y = h1;
        __nv_bfloat162 l2;
        l2.x = __float2bfloat16_rn(y[2 * j] - __bfloat162float(h0));
        l2.y = __float2bfloat16_rn(y[2 * j + 1] - __bfloat162float(h1));
        *(__nv_bfloat162*)(Ahi + rowoff + tid * 8 + 2 * j) = h2;
        *(__nv_bfloat162*)(Alo + rowoff + tid * 8 + 2 * j) = l2;
    }
}

// ---------------------------------------------------------------------------
extern "C" void kernel_launch(void* const* d_in, const int* in_sizes, int n_in,
                              void* d_out, int out_size) {
    (void)in_sizes; (void)n_in; (void)out_size;
    const float* query  = (const float*)d_in[0];   // [B, TQ, UNITS]
    const float* values = (const float*)d_in[1];   // [B, TV, D]
    const float* Wk     = (const float*)d_in[2];   // [D, UNITS]
    const float* Wb     = (const float*)d_in[3];   // [UNITS]

    float* context = (float*)d_out;                               // [B, TQ, D]
    float* align   = (float*)d_out + (size_t)B_DIM * TQ * D_DIM;  // [B, TQ, TV]

    bf16 *Qhi, *Qlo, *Vhi, *Vlo, *VThi, *VTlo, *Khi, *Klo, *WThi, *WTlo, *Ahi, *Alo;
    cudaGetSymbolAddress((void**)&Qhi, g_Qhi);   cudaGetSymbolAddress((void**)&Qlo, g_Qlo);
    cudaGetSymbolAddress((void**)&Vhi, g_Vhi);   cudaGetSymbolAddress((void**)&Vlo, g_Vlo);
    cudaGetSymbolAddress((void**)&VThi, g_VThi); cudaGetSymbolAddress((void**)&VTlo, g_VTlo);
    cudaGetSymbolAddress((void**)&Khi, g_Khi);   cudaGetSymbolAddress((void**)&Klo, g_Klo);
    cudaGetSymbolAddress((void**)&WThi, g_WThi); cudaGetSymbolAddress((void**)&WTlo, g_WTlo);
    cudaGetSymbolAddress((void**)&Ahi, g_Ahi);   cudaGetSymbolAddress((void**)&Alo, g_Alo);

    cudaFuncSetAttribute(hmma_gemm_kernel<0>,
                         cudaFuncAttributeMaxDynamicSharedMemorySize, SM_TOTAL);
    cudaFuncSetAttribute(hmma_gemm_kernel<1>,
                         cudaFuncAttributeMaxDynamicSharedMemorySize, SM_TOTAL);

    // 1) splits
    split_kernel<<<(unsigned)(NQ / 4 / 256), 256>>>(query, Qhi, Qlo, NQ / 4);
    {
        dim3 grid(D_DIM / 32, TV / 32, B_DIM);
        transpose_split_kernel<<<grid, dim3(32, 8)>>>(values, Vhi, Vlo, VThi, VTlo,
                                                      TV, D_DIM);
    }
    {
        dim3 grid(UNITS / 32, D_DIM / 32, 1);
        transpose_split_kernel<<<grid, dim3(32, 8)>>>(Wk, nullptr, nullptr, WThi, WTlo,
                                                      D_DIM, UNITS);
    }

    // 2) keys = values @ W + b  (M=B*TV, N=UNITS, K=D), split epilogue
    {
        dim3 grid(UNITS / 128, (B_DIM * TV) / 128, 1);
        hmma_gemm_kernel<1><<<grid, 128, SM_TOTAL>>>(
            Vhi, Vlo, WThi, WTlo, Wb, nullptr, Khi, Klo,
            B_DIM * TV, UNITS, D_DIM, 0, 0, 0);
    }

    // 3) score = Q @ K^T per batch -> align buffer (fp32)
    {
        dim3 grid(TV / 128, TQ / 128, B_DIM);
        hmma_gemm_kernel<0><<<grid, 128, SM_TOTAL>>>(
            Qhi, Qlo, Khi, Klo, nullptr, align, nullptr, nullptr,
            TQ, TV, UNITS,
            (size_t)TQ * UNITS, (size_t)TV * UNITS, (size_t)TQ * TV);
    }

    // 4) softmax in place + split emit
    softmax_split_kernel<<<B_DIM * TQ, 256>>>(align, Ahi, Alo);

    // 5) context = align @ values per batch (B operand = values^T [D, TV])
    {
        dim3 grid(D_DIM / 128, TQ / 128, B_DIM);
        hmma_gemm_kernel<0><<<grid, 128, SM_TOTAL>>>(
            Ahi, Alo, VThi, VTlo, nullptr, context, nullptr, nullptr,
            TQ, D_DIM, TV,
            (size_t)TQ * TV, (size_t)D_DIM * TV, (size_t)TQ * D_DIM);
    }
}

// round 13
// speedup vs baseline: 1.3428x; 1.3428x over previous
#include <cuda_runtime.h>
#include <cuda_bf16.h>
#include <cstdint>
#include <cstddef>

// ---------------------------------------------------------------------------
// LuongAttention via bf16 hi/lo 3-pass mma.sync (HMMA).
// R13 = R9 (128x128 CTA, 2x4 warps 64x32, 3-stage mbarrier ring, 2 CTAs/SM)
//       + lane0-elect consumed-arrive (count 8, kills 32-lane ATOMS serial)
//       + incremental global pointers in load_stage (kills per-iter 64-bit
//         address mults that drove alu to 13.7%).
// ---------------------------------------------------------------------------

#define B_DIM 16
#define TQ 2048
#define TV 2048
#define D_DIM 1024
#define UNITS 1024

typedef __nv_bfloat16 bf16;

#define NQ ((size_t)B_DIM * TQ * UNITS)
#define NV ((size_t)B_DIM * TV * D_DIM)
#define NK ((size_t)B_DIM * TV * UNITS)
#define NS ((size_t)B_DIM * TQ * TV)

__device__ bf16 g_Qhi[NQ], g_Qlo[NQ];
__device__ bf16 g_Vhi[NV], g_Vlo[NV];
__device__ bf16 g_VThi[NV], g_VTlo[NV];     // values^T per batch: [D, TV]
__device__ bf16 g_Khi[NK], g_Klo[NK];
__device__ bf16 g_WThi[D_DIM * UNITS], g_WTlo[D_DIM * UNITS];   // W^T: [U, D]
__device__ bf16 g_Ahi[NS], g_Alo[NS];

// ---------------------------------------------------------------------------
__device__ __forceinline__ uint32_t smem_u32(const void* p) {
    uint32_t a;
    asm("{ .reg .u64 t; cvta.to.shared.u64 t, %1; cvt.u32.u64 %0, t; }"
        : "=r"(a) : "l"(p));
    return a;
}

#define CP_ASYNC16(dst, src) \
    asm volatile("cp.async.cg.shared.global [%0], [%1], 16;" \
                 :: "r"(dst), "l"(src) : "memory")

#define MBAR_INIT(a, c) \
    asm volatile("mbarrier.init.shared.b64 [%0], %1;" :: "r"(a), "r"(c) : "memory")
#define MBAR_ARRIVE(a) \
    asm volatile("mbarrier.arrive.shared.b64 _, [%0];" :: "r"(a) : "memory")
#define CP_MBAR_ARRIVE(a) \
    asm volatile("cp.async.mbarrier.arrive.noinc.shared.b64 [%0];" :: "r"(a) : "memory")

#define MBAR_WAIT(a, par) do {                                            \
    uint32_t _m = (a), _p = (uint32_t)(par), _d;                          \
    asm volatile("{\n\t.reg .pred p;\n\t"                                 \
        "mbarrier.try_wait.parity.acquire.cta.shared::cta.b64 p, [%1], %2;\n\t" \
        "selp.b32 %0, 1, 0, p;\n\t}" : "=r"(_d) : "r"(_m), "r"(_p) : "memory"); \
    if (!_d) {                                                            \
        asm volatile("{\n\t.reg .pred P1;\n\t"                            \
            "WL_%=:\n\t"                                                  \
            "mbarrier.try_wait.parity.acquire.cta.shared::cta.b64 P1, [%0], %1, 0x989680;\n\t" \
            "@P1 bra.uni WD_%=;\n\tbra.uni WL_%=;\n\tWD_%=:\n\t}"         \
            :: "r"(_m), "r"(_p) : "memory");                              \
    } } while (0)

__device__ __forceinline__ void ldsm4(uint32_t& r0, uint32_t& r1,
                                      uint32_t& r2, uint32_t& r3, uint32_t addr) {
    asm volatile("ldmatrix.sync.aligned.m8n8.x4.shared.b16 {%0,%1,%2,%3}, [%4];"
                 : "=r"(r0), "=r"(r1), "=r"(r2), "=r"(r3) : "r"(addr));
}

__device__ __forceinline__ void mma16816(float* d, const uint32_t* a, const uint32_t* b) {
    asm volatile("mma.sync.aligned.m16n8k16.row.col.f32.bf16.bf16.f32 "
                 "{%0,%1,%2,%3},{%4,%5,%6,%7},{%8,%9},{%0,%1,%2,%3};"
                 : "+f"(d[0]), "+f"(d[1]), "+f"(d[2]), "+f"(d[3])
                 : "r"(a[0]), "r"(a[1]), "r"(a[2]), "r"(a[3]), "r"(b[0]), "r"(b[1]));
}

// ---------------------------------------------------------------------------
// SMEM: rows of 64 B (32 bf16), XOR swizzle: 16B-chunk c of row r at position
// c ^ ((r>>1)&3). Stage: Ahi|Alo|Bhi|Blo, each 8192 B. Stage = 32 KB, x3 ring.
// Barriers: produced[3] (count 256), consumed[3] (count 8, lane0 arrives).
// ---------------------------------------------------------------------------
#define OFF_AHI 0u
#define OFF_ALO 8192u
#define OFF_BHI 16384u
#define OFF_BLO 24576u
#define ST_SZ   32768u
#define SM_PROD (3u * ST_SZ)
#define SM_CONS (3u * ST_SZ + 24u)
#define SM_TOTAL (3u * ST_SZ + 64u)

// C[M,N] = (Ahi+Alo)[M,K] @ (Bhi+Blo)[N,K]^T  (3-pass), batched via blockIdx.z.
// CTA tile 128x128, warp tile 64x32 (2x4 warps). EPI=0: fp32 C. EPI=1: +bias,
// split to Chi/Clo bf16.
template <int EPI>
__global__ void __launch_bounds__(256, 2)
hmma_gemm_kernel(const bf16* __restrict__ Ahi_, const bf16* __restrict__ Alo_,
                 const bf16* __restrict__ Bhi_, const bf16* __restrict__ Blo_,
                 const float* __restrict__ bias,
                 float* __restrict__ Cf_, bf16* __restrict__ Chi_, bf16* __restrict__ Clo_,
                 int M, int N, int K,
                 size_t sA, size_t sB, size_t sC) {
    extern __shared__ char smc[];
    const uint32_t sb = smem_u32(smc);
    const int tid = threadIdx.x, lane = tid & 31, wid = tid >> 5;
    const int wm = wid >> 2, wn = wid & 3;        // 2x4 warps
    const int bn = blockIdx.x, bm = blockIdx.y, bz = blockIdx.z;

    float acc[4][4][4];
#pragma unroll
    for (int i = 0; i < 4; ++i)
#pragma unroll
        for (int j = 0; j < 4; ++j)
#pragma unroll
            for (int p = 0; p < 4; ++p) acc[i][j][p] = 0.0f;

    // ---- writer coords ----
    const int lr = tid >> 2;                  // 0..63
    const int wc = tid & 3;                   // chunk 0..3
    const int wsw = (lr >> 1) & 3;
    const uint32_t so0 = (uint32_t)lr * 64 + (uint32_t)((wc ^ wsw) * 16);
    const uint32_t so1 = (uint32_t)(lr + 64) * 64 + (uint32_t)((wc ^ wsw) * 16);
    const int le = wc * 8;

    // incremental global pointers (advance +32 elements per stage fill;
    // stage fills are issued in strictly increasing kt order)
    const bf16* pA0 = Ahi_ + (size_t)bz * sA + (size_t)(bm * 128 + lr) * K + le;
    const bf16* pA1 = Ahi_ + (size_t)bz * sA + (size_t)(bm * 128 + lr + 64) * K + le;
    const bf16* pAl0 = Alo_ + (size_t)bz * sA + (size_t)(bm * 128 + lr) * K + le;
    const bf16* pAl1 = Alo_ + (size_t)bz * sA + (size_t)(bm * 128 + lr + 64) * K + le;
    const bf16* pB0 = Bhi_ + (size_t)bz * sB + (size_t)(bn * 128 + lr) * K + le;
    const bf16* pB1 = Bhi_ + (size_t)bz * sB + (size_t)(bn * 128 + lr + 64) * K + le;
    const bf16* pBl0 = Blo_ + (size_t)bz * sB + (size_t)(bn * 128 + lr) * K + le;
    const bf16* pBl1 = Blo_ + (size_t)bz * sB + (size_t)(bn * 128 + lr + 64) * K + le;

    // ---- reader coords ----
    const int row0a = wm * 64 + (lane & 15);
    const int c0a = lane >> 4;
    const int sa = (row0a >> 1) & 3;
    const uint32_t axk[2] = { (uint32_t)(((c0a + 0) ^ sa) * 16),
                              (uint32_t)(((c0a + 2) ^ sa) * 16) };
    const uint32_t abase = (uint32_t)row0a * 64;
    const int row0b = wn * 32 + ((lane >> 4) << 3) + (lane & 7);
    const int c0b = (lane >> 3) & 1;
    const int sbw = (row0b >> 1) & 3;
    const uint32_t bxk[2] = { (uint32_t)(((c0b + 0) ^ sbw) * 16),
                              (uint32_t)(((c0b + 2) ^ sbw) * 16) };
    const uint32_t bbase = (uint32_t)row0b * 64;

    const int nk = K / 32;

    auto load_stage = [&](uint32_t st) {
        CP_ASYNC16(st + OFF_AHI + so0, pA0);
        CP_ASYNC16(st + OFF_AHI + so1, pA1);
        CP_ASYNC16(st + OFF_ALO + so0, pAl0);
        CP_ASYNC16(st + OFF_ALO + so1, pAl1);
        CP_ASYNC16(st + OFF_BHI + so0, pB0);
        CP_ASYNC16(st + OFF_BHI + so1, pB1);
        CP_ASYNC16(st + OFF_BLO + so0, pBl0);
        CP_ASYNC16(st + OFF_BLO + so1, pBl1);
        pA0 += 32; pA1 += 32; pAl0 += 32; pAl1 += 32;
        pB0 += 32; pB1 += 32; pBl0 += 32; pBl1 += 32;
    };

    // ---- barrier init, prologue fills for stages 0 and 1 ----
    if (tid == 0) {
#pragma unroll
        for (int s = 0; s < 3; ++s) {
            MBAR_INIT(sb + SM_PROD + s * 8, 256);   // every thread's cp.asyncs
            MBAR_INIT(sb + SM_CONS + s * 8, 8);     // lane0 of each warp
        }
    }
    __syncthreads();

    load_stage(sb);
    CP_MBAR_ARRIVE(sb + SM_PROD + 0);
    load_stage(sb + ST_SZ);
    CP_MBAR_ARRIVE(sb + SM_PROD + 8);

    int rs = 0, rp = 0;        // read stage/parity
    int ws = 2, wp = 1;        // write stage/parity

    for (int kt = 0; kt < nk; ++kt) {
        const uint32_t s0 = sb + (uint32_t)rs * ST_SZ;
        MBAR_WAIT(sb + SM_PROD + rs * 8, rp);

#pragma unroll
        for (int ks = 0; ks < 2; ++ks) {
            uint32_t ahf[4][4], bhf[2][4], blf[2][4], alf[4][4];

            // critical-path ldsm first: bhf x2, ahf[0]
#pragma unroll
            for (int np = 0; np < 2; ++np)
                ldsm4(bhf[np][0], bhf[np][1], bhf[np][2], bhf[np][3],
                      s0 + OFF_BHI + bbase + (uint32_t)(np * 16 * 64) + bxk[ks]);
            ldsm4(ahf[0][0], ahf[0][1], ahf[0][2], ahf[0][3],
                  s0 + OFF_AHI + abase + axk[ks]);

            // pass 1 (hi*hi): pace 1 ldsm per 4 MMAs
#pragma unroll
            for (int mi = 0; mi < 4; ++mi) {
                if (mi < 3) {
                    ldsm4(ahf[mi + 1][0], ahf[mi + 1][1], ahf[mi + 1][2], ahf[mi + 1][3],
                          s0 + OFF_AHI + abase + (uint32_t)((mi + 1) * 16 * 64) + axk[ks]);
                } else {
#pragma unroll
                    for (int np = 0; np < 2; ++np)
                        ldsm4(blf[np][0], blf[np][1], blf[np][2], blf[np][3],
                              s0 + OFF_BLO + bbase + (uint32_t)(np * 16 * 64) + bxk[ks]);
                }
#pragma unroll
                for (int ni = 0; ni < 4; ++ni)
                    mma16816(acc[mi][ni], ahf[mi], &bhf[ni >> 1][(ni & 1) * 2]);
            }

            // pass 2 (hi*lo): pace alf ldsm (used only in pass 3)
#pragma unroll
            for (int mi = 0; mi < 4; ++mi) {
                ldsm4(alf[mi][0], alf[mi][1], alf[mi][2], alf[mi][3],
                      s0 + OFF_ALO + abase + (uint32_t)(mi * 16 * 64) + axk[ks]);
#pragma unroll
                for (int ni = 0; ni < 4; ++ni)
                    mma16816(acc[mi][ni], ahf[mi], &blf[ni >> 1][(ni & 1) * 2]);
            }

            // producer block once per kt, between pass2 and pass3 of ks==0
            if (ks == 0 && kt + 2 < nk) {
                MBAR_WAIT(sb + SM_CONS + ws * 8, wp);
                load_stage(sb + (uint32_t)ws * ST_SZ);
                CP_MBAR_ARRIVE(sb + SM_PROD + ws * 8);
            }

            // pass 3 (lo*hi): all frags resident, dense MMA
#pragma unroll
            for (int mi = 0; mi < 4; ++mi)
#pragma unroll
                for (int ni = 0; ni < 4; ++ni)
                    mma16816(acc[mi][ni], alf[mi], &bhf[ni >> 1][(ni & 1) * 2]);
        }

        // reads of stage rs complete; mma.sync is warp-synchronous, so lane0
        // arriving proves the whole warp's ldsm of this stage are drained.
        if (lane == 0) MBAR_ARRIVE(sb + SM_CONS + rs * 8);

        if (++rs == 3) { rs = 0; rp ^= 1; }
        if (++ws == 3) { ws = 0; wp ^= 1; }
    }

    // ---- epilogue ----
    const int row0 = bm * 128 + wm * 64 + (lane >> 2);
    const int col0 = bn * 128 + wn * 32 + (lane & 3) * 2;
#pragma unroll
    for (int mi = 0; mi < 4; ++mi)
#pragma unroll
        for (int h = 0; h < 2; ++h) {
            const int row = row0 + mi * 16 + h * 8;
#pragma unroll
            for (int ni = 0; ni < 4; ++ni) {
                const int col = col0 + ni * 8;
                const float v0 = acc[mi][ni][2 * h];
                const float v1 = acc[mi][ni][2 * h + 1];
                if (EPI == 0) {
                    float2 o; o.x = v0; o.y = v1;
                    *(float2*)(Cf_ + (size_t)bz * sC + (size_t)row * N + col) = o;
                } else {
                    const float f0 = v0 + bias[col];
                    const float f1 = v1 + bias[col + 1];
                    const bf16 h0 = __float2bfloat16_rn(f0);
                    const bf16 h1 = __float2bfloat16_rn(f1);
                    __nv_bfloat162 hh, ll;
                    hh.x = h0; hh.y = h1;
                    ll.x = __float2bfloat16_rn(f0 - __bfloat162float(h0));
                    ll.y = __float2bfloat16_rn(f1 - __bfloat162float(h1));
                    const size_t o = (size_t)row * N + col;
                    *(__nv_bfloat162*)(Chi_ + o) = hh;
                    *(__nv_bfloat162*)(Clo_ + o) = ll;
                }
            }
        }
}

// ---------------------------------------------------------------------------
__global__ void split_kernel(const float* __restrict__ x,
                             bf16* __restrict__ hi, bf16* __restrict__ lo, size_t n4) {
    const size_t i = (size_t)blockIdx.x * blockDim.x + threadIdx.x;
    if (i >= n4) return;
    const float4 v = ((const float4*)x)[i];
    const float f[4] = {v.x, v.y, v.z, v.w};
    __nv_bfloat162 h2[2], l2[2];
#pragma unroll
    for (int j = 0; j < 2; ++j) {
        const bf16 h0 = __float2bfloat16_rn(f[2 * j]);
        const bf16 h1 = __float2bfloat16_rn(f[2 * j + 1]);
        h2[j].x = h0; h2[j].y = h1;
        l2[j].x = __float2bfloat16_rn(f[2 * j] - __bfloat162float(h0));
        l2[j].y = __float2bfloat16_rn(f[2 * j + 1] - __bfloat162float(h1));
    }
    ((__nv_bfloat162*)hi)[2 * i] = h2[0];
    ((__nv_bfloat162*)hi)[2 * i + 1] = h2[1];
    ((__nv_bfloat162*)lo)[2 * i] = l2[0];
    ((__nv_bfloat162*)lo)[2 * i + 1] = l2[1];
}

__global__ void transpose_split_kernel(const float* __restrict__ in,
                                       bf16* __restrict__ shi, bf16* __restrict__ slo,
                                       bf16* __restrict__ thi, bf16* __restrict__ tlo,
                                       int rows, int cols) {
    __shared__ float tile[32][33];
    const int tx = threadIdx.x, ty = threadIdx.y;
    const int bx = blockIdx.x, by = blockIdx.y, bz = blockIdx.z;
    const size_t base = (size_t)bz * rows * cols;
    const int x = bx * 32 + tx;

#pragma unroll
    for (int j = 0; j < 4; ++j) {
        const int r = by * 32 + ty + j * 8;
        const float v = in[base + (size_t)r * cols + x];
        tile[ty + j * 8][tx] = v;
        if (shi) {
            const bf16 h = __float2bfloat16_rn(v);
            shi[base + (size_t)r * cols + x] = h;
            slo[base + (size_t)r * cols + x] =
                __float2bfloat16_rn(v - __bfloat162float(h));
        }
    }
    __syncthreads();
#pragma unroll
    for (int j = 0; j < 4; ++j) {
        const int r = ty + j * 8;
        const float v = tile[tx][r];
        const int orow = bx * 32 + r;
        const int ocol = by * 32 + tx;
        const bf16 h = __float2bfloat16_rn(v);
        thi[base + (size_t)orow * rows + ocol] = h;
        tlo[base + (size_t)orow * rows + ocol] =
            __float2bfloat16_rn(v - __bfloat162float(h));
    }
}

__global__ void softmax_split_kernel(float* __restrict__ S,
                                     bf16* __restrict__ Ahi, bf16* __restrict__ Alo) {
    const int tid = threadIdx.x;
    const size_t rowoff = (size_t)blockIdx.x * TV;
    float* p = S + rowoff;

    float v[8];
    {
        const float4 x0 = *(const float4*)(p + tid * 8);
        const float4 x1 = *(const float4*)(p + tid * 8 + 4);
        v[0] = x0.x; v[1] = x0.y; v[2] = x0.z; v[3] = x0.w;
        v[4] = x1.x; v[5] = x1.y; v[6] = x1.z; v[7] = x1.w;
    }

    __shared__ float red[16];
    const int lane = tid & 31, wid = tid >> 5;

    float m = v[0];
#pragma unroll
    for (int i = 1; i < 8; ++i) m = fmaxf(m, v[i]);
#pragma unroll
    for (int o = 16; o > 0; o >>= 1) m = fmaxf(m, __shfl_xor_sync(0xffffffffu, m, o));
    if (lane == 0) red[wid] = m;
    __syncthreads();
    if (tid == 0) {
        float mm = red[0];
#pragma unroll
        for (int i = 1; i < 8; ++i) mm = fmaxf(mm, red[i]);
        red[0] = mm;
    }
    __syncthreads();
    m = red[0];

    float s = 0.0f;
#pragma unroll
    for (int i = 0; i < 8; ++i) { v[i] = __expf(v[i] - m); s += v[i]; }
#pragma unroll
    for (int o = 16; o > 0; o >>= 1) s += __shfl_xor_sync(0xffffffffu, s, o);
    if (lane == 0) red[8 + wid] = s;
    __syncthreads();
    if (tid == 0) {
        float ss = red[8];
#pragma unroll
        for (int i = 1; i < 8; ++i) ss += red[8 + i];
        red[8] = ss;
    }
    __syncthreads();
    const float inv = 1.0f / red[8];

    float y[8];
#pragma unroll
    for (int i = 0; i < 8; ++i) y[i] = v[i] * inv;

    float4 o0, o1;
    o0.x = y[0]; o0.y = y[1]; o0.z = y[2]; o0.w = y[3];
    o1.x = y[4]; o1.y = y[5]; o1.z = y[6]; o1.w = y[7];
    *(float4*)(p + tid * 8) = o0;
    *(float4*)(p + tid * 8 + 4) = o1;

#pragma unroll
    for (int j = 0; j < 4; ++j) {
        const bf16 h0 = __float2bfloat16_rn(y[2 * j]);
        const bf16 h1 = __float2bfloat16_rn(y[2 * j + 1]);
        __nv_bfloat162 h2; h2.x = h0; h2.y = h1;
        __nv_bfloat162 l2;
        l2.x = __float2bfloat16_rn(y[2 * j] - __bfloat162float(h0));
        l2.y = __float2bfloat16_rn(y[2 * j + 1] - __bfloat162float(h1));
        *(__nv_bfloat162*)(Ahi + rowoff + tid * 8 + 2 * j) = h2;
        *(__nv_bfloat162*)(Alo + rowoff + tid * 8 + 2 * j) = l2;
    }
}

// ---------------------------------------------------------------------------
extern "C" void kernel_launch(void* const* d_in, const int* in_sizes, int n_in,
                              void* d_out, int out_size) {
    (void)in_sizes; (void)n_in; (void)out_size;
    const float* query  = (const float*)d_in[0];   // [B, TQ, UNITS]
    const float* values = (const float*)d_in[1];   // [B, TV, D]
    const float* Wk     = (const float*)d_in[2];   // [D, UNITS]
    const float* Wb     = (const float*)d_in[3];   // [UNITS]

    float* context = (float*)d_out;                               // [B, TQ, D]
    float* align   = (float*)d_out + (size_t)B_DIM * TQ * D_DIM;  // [B, TQ, TV]

    bf16 *Qhi, *Qlo, *Vhi, *Vlo, *VThi, *VTlo, *Khi, *Klo, *WThi, *WTlo, *Ahi, *Alo;
    cudaGetSymbolAddress((void**)&Qhi, g_Qhi);   cudaGetSymbolAddress((void**)&Qlo, g_Qlo);
    cudaGetSymbolAddress((void**)&Vhi, g_Vhi);   cudaGetSymbolAddress((void**)&Vlo, g_Vlo);
    cudaGetSymbolAddress((void**)&VThi, g_VThi); cudaGetSymbolAddress((void**)&VTlo, g_VTlo);
    cudaGetSymbolAddress((void**)&Khi, g_Khi);   cudaGetSymbolAddress((void**)&Klo, g_Klo);
    cudaGetSymbolAddress((void**)&WThi, g_WThi); cudaGetSymbolAddress((void**)&WTlo, g_WTlo);
    cudaGetSymbolAddress((void**)&Ahi, g_Ahi);   cudaGetSymbolAddress((void**)&Alo, g_Alo);

    cudaFuncSetAttribute(hmma_gemm_kernel<0>,
                         cudaFuncAttributeMaxDynamicSharedMemorySize, SM_TOTAL);
    cudaFuncSetAttribute(hmma_gemm_kernel<1>,
                         cudaFuncAttributeMaxDynamicSharedMemorySize, SM_TOTAL);

    // 1) splits
    split_kernel<<<(unsigned)(NQ / 4 / 256), 256>>>(query, Qhi, Qlo, NQ / 4);
    {
        dim3 grid(D_DIM / 32, TV / 32, B_DIM);
        transpose_split_kernel<<<grid, dim3(32, 8)>>>(values, Vhi, Vlo, VThi, VTlo,
                                                      TV, D_DIM);
    }
    {
        dim3 grid(UNITS / 32, D_DIM / 32, 1);
        transpose_split_kernel<<<grid, dim3(32, 8)>>>(Wk, nullptr, nullptr, WThi, WTlo,
                                                      D_DIM, UNITS);
    }

    // 2) keys = values @ W + b  (M=B*TV, N=UNITS, K=D), split epilogue
    {
        dim3 grid(UNITS / 128, (B_DIM * TV) / 128, 1);
        hmma_gemm_kernel<1><<<grid, 256, SM_TOTAL>>>(
            Vhi, Vlo, WThi, WTlo, Wb, nullptr, Khi, Klo,
            B_DIM * TV, UNITS, D_DIM, 0, 0, 0);
    }

    // 3) score = Q @ K^T per batch -> align buffer (fp32)
    {
        dim3 grid(TV / 128, TQ / 128, B_DIM);
        hmma_gemm_kernel<0><<<grid, 256, SM_TOTAL>>>(
            Qhi, Qlo, Khi, Klo, nullptr, align, nullptr, nullptr,
            TQ, TV, UNITS,
            (size_t)TQ * UNITS, (size_t)TV * UNITS, (size_t)TQ * TV);
    }

    // 4) softmax in place + split emit
    softmax_split_kernel<<<B_DIM * TQ, 256>>>(align, Ahi, Alo);

    // 5) context = align @ values per batch (B operand = values^T [D, TV])
    {
        dim3 grid(D_DIM / 128, TQ / 128, B_DIM);
        hmma_gemm_kernel<0><<<grid, 256, SM_TOTAL>>>(
            Ahi, Alo, VThi, VTlo, nullptr, context, nullptr, nullptr,
            TQ, D_DIM, TV,
            (size_t)TQ * TV, (size_t)D_DIM * TV, (size_t)TQ * D_DIM);
    }
}